// round 13
// baseline (speedup 1.0000x reference)
#include <cuda_runtime.h>
#include <cuda_fp16.h>
#include <cstdint>

#define B_ROWS 16384
#define IN_DIM 64
#define OUT_DIM 4096
#define BM 128
#define BN 256

typedef unsigned long long ull;

// ---- device-global scratch (alloc-guard-safe) ----
__device__ __half g_xh[B_ROWS * IN_DIM];
__device__ __half g_ch[OUT_DIM * IN_DIM];
__device__ float g_xn[B_ROWS];
__device__ float g_cn[OUT_DIM];
__device__ float g_iv[OUT_DIM];

// ---- smem layout (bytes) ----
#define SA      0            // 16KB (128 rows x 128B)
#define SB      16384        // 32KB (256 rows x 128B)
#define S_XN    49152        // 512B
#define S_CN    49664        // 1KB (256 f32)
#define S_IV    50688        // 1KB
#define S_STAGE 51712        // 8 warps x 2KB
#define SMEM_TOTAL 68096

__device__ __forceinline__ uint32_t s2u(const void* p) {
    uint32_t a;
    asm("{ .reg .u64 t; cvta.to.shared.u64 t, %1; cvt.u32.u64 %0, t; }" : "=r"(a) : "l"(p));
    return a;
}
__device__ __forceinline__ void ldm_x4(uint32_t* r, uint32_t addr) {
    asm volatile("ldmatrix.sync.aligned.m8n8.x4.shared.b16 {%0,%1,%2,%3}, [%4];"
                 : "=r"(r[0]), "=r"(r[1]), "=r"(r[2]), "=r"(r[3]) : "r"(addr));
}
__device__ __forceinline__ void stm_x4(uint32_t addr, uint32_t r0, uint32_t r1,
                                       uint32_t r2, uint32_t r3) {
    asm volatile("stmatrix.sync.aligned.m8n8.x4.shared.b16 [%0], {%1,%2,%3,%4};"
                 :: "r"(addr), "r"(r0), "r"(r1), "r"(r2), "r"(r3) : "memory");
}
__device__ __forceinline__ void mma_h(uint32_t* c, const uint32_t* a,
                                      uint32_t b0, uint32_t b1) {
    asm volatile(
        "mma.sync.aligned.m16n8k16.row.col.f16.f16.f16.f16 "
        "{%0,%1}, {%2,%3,%4,%5}, {%6,%7}, {%0,%1};"
        : "+r"(c[0]), "+r"(c[1])
        : "r"(a[0]), "r"(a[1]), "r"(a[2]), "r"(a[3]), "r"(b0), "r"(b1));
}
__device__ __forceinline__ float ex2a(float x) {
    float r;
    asm("ex2.approx.f32 %0, %1;" : "=f"(r) : "f"(x));
    return r;
}
__device__ __forceinline__ ull pk2(float lo, float hi) {
    ull r;
    asm("mov.b64 %0, {%1, %2};" : "=l"(r) : "f"(lo), "f"(hi));
    return r;
}
__device__ __forceinline__ void upk2(ull v, float& lo, float& hi) {
    asm("mov.b64 {%0, %1}, %2;" : "=f"(lo), "=f"(hi) : "l"(v));
}
__device__ __forceinline__ ull fma2p(ull a, ull b, ull c) {
    ull r;
    asm("fma.rn.f32x2 %0, %1, %2, %3;" : "=l"(r) : "l"(a), "l"(b), "l"(c));
    return r;
}
__device__ __forceinline__ ull mul2p(ull a, ull b) {
    ull r;
    asm("mul.rn.f32x2 %0, %1, %2;" : "=l"(r) : "l"(a), "l"(b));
    return r;
}
__device__ __forceinline__ ull add2p(ull a, ull b) {
    ull r;
    asm("add.rn.f32x2 %0, %1, %2;" : "=l"(r) : "l"(a), "l"(b));
    return r;
}

// ---- prep (fused): f32 -> fp16, row norms, inv_sigma2 ----
__global__ void prep_all(const float* __restrict__ x, const float* __restrict__ c,
                         const float* __restrict__ ls) {
    int gw = (blockIdx.x * blockDim.x + threadIdx.x) >> 5;
    int lane = threadIdx.x & 31;
    const float* src;
    __half2* dst;
    int row;
    if (gw < B_ROWS) {
        row = gw; src = x; dst = (__half2*)g_xh;
    } else {
        row = gw - B_ROWS;
        if (row >= OUT_DIM) return;
        src = c; dst = (__half2*)g_ch;
    }
    float2 v = ((const float2*)src)[row * 32 + lane];
    dst[row * 32 + lane] = __floats2half2_rn(v.x, v.y);
    float s = v.x * v.x + v.y * v.y;
#pragma unroll
    for (int o = 16; o; o >>= 1) s += __shfl_xor_sync(0xffffffffu, s, o);
    if (lane == 0) {
        if (gw < B_ROWS) g_xn[row] = s;
        else { g_cn[row] = s; g_iv[row] = __expf(-2.0f * ls[row]); }
    }
}

// ---- main: 128x256 tile, 64x64 warp tiles, f16-acc mma, f32x2 epilogue ----
__global__ void __launch_bounds__(256, 2)
rbf_mma(float* __restrict__ out) {
    extern __shared__ char smem[];
    const uint32_t sb = s2u(smem);
    const int tid = threadIdx.x;
    const int bn = blockIdx.x * BN;
    const int bm = blockIdx.y * BM;

    // ---- global -> smem, XOR-swizzled (16B chunk q -> q ^ (row&7)) ----
    {
        const uint4* ax = (const uint4*)(g_xh + (size_t)bm * IN_DIM);
        const uint4* bc = (const uint4*)(g_ch + (size_t)bn * IN_DIM);
#pragma unroll
        for (int l = tid; l < 1024; l += 256) {
            int row = l >> 3, q = l & 7;
            *(uint4*)(smem + SA + row * 128 + ((q ^ (row & 7)) << 4)) = ax[l];
        }
#pragma unroll
        for (int l = tid; l < 2048; l += 256) {
            int row = l >> 3, q = l & 7;
            *(uint4*)(smem + SB + row * 128 + ((q ^ (row & 7)) << 4)) = bc[l];
        }
        if (tid < 128) ((float*)(smem + S_XN))[tid] = g_xn[bm + tid];
        ((float*)(smem + S_CN))[tid] = g_cn[bn + tid];
        ((float*)(smem + S_IV))[tid] = g_iv[bn + tid];
    }
    __syncthreads();

    const int wid = tid >> 5, lane = tid & 31;
    const int wm = wid >> 2, wn = wid & 3;   // 2x4 warp grid, 64x64 warp tiles
    const int lrow = lane & 15;
    const int ksel = lane >> 4;
    const int szk = lrow & 7;

    uint32_t aBase[4], bBase[4];
#pragma unroll
    for (int t = 0; t < 4; t++) {
        aBase[t] = sb + SA + (wm * 64 + t * 16 + lrow) * 128;
        bBase[t] = sb + SB + (wn * 64 + t * 16 + lrow) * 128;
    }

    uint32_t acc[4][8][2];                   // f16x2-packed accumulators
#pragma unroll
    for (int i = 0; i < 4; i++)
#pragma unroll
        for (int j = 0; j < 8; j++) { acc[i][j][0] = 0u; acc[i][j][1] = 0u; }

#pragma unroll
    for (int ks = 0; ks < 4; ks++) {
        const int kc = ks * 2 + ksel;
        const uint32_t ko = (uint32_t)((kc ^ szk) << 4);
        uint32_t Ah[4][4], Bh[4][4];
#pragma unroll
        for (int t = 0; t < 4; t++) ldm_x4(Ah[t], aBase[t] + ko);
#pragma unroll
        for (int t = 0; t < 4; t++) ldm_x4(Bh[t], bBase[t] + ko);
#pragma unroll
        for (int mt = 0; mt < 4; mt++)
#pragma unroll
            for (int p = 0; p < 4; p++) {
                mma_h(acc[mt][p * 2 + 0], Ah[mt], Bh[p][0], Bh[p][2]);
                mma_h(acc[mt][p * 2 + 1], Ah[mt], Bh[p][1], Bh[p][3]);
            }
    }

    // ---- epilogue: swizzled stage; packed f32x2 math; no clamp ----
    const float* xn_s = (const float*)(smem + S_XN);
    const float* cn_s = (const float*)(smem + S_CN);
    const float* iv_s = (const float*)(smem + S_IV);
    const float L2E = 1.4426950408889634f;

    const int prow = lane >> 3;          // 0..3
    const int pcol = lane & 7;           // matrix index / col-chunk

    ull ncn2[4], ivl2[4];                // packed -cn pairs, packed iv*log2e pairs
#pragma unroll
    for (int j = 0; j < 4; j++) {
        int col = wn * 64 + pcol * 8 + j * 2;
        ncn2[j] = pk2(-cn_s[col], -cn_s[col + 1]);
        ivl2[j] = pk2(iv_s[col] * L2E, iv_s[col + 1] * L2E);
    }
    const ull TWO2 = pk2(2.0f, 2.0f);

    const uint32_t wstage = sb + S_STAGE + wid * 2048;
    const int m_loc = lane >> 3;
    const int rr_s = lane & 7;

#pragma unroll
    for (int mt = 0; mt < 4; mt++) {
#pragma unroll
        for (int g = 0; g < 2; g++)
#pragma unroll
            for (int qb = 0; qb < 8; qb += 4) {
                int m = qb + m_loc;
                uint32_t a = wstage + (uint32_t)((g * 8 + m) * 128 +
                             (((rr_s + m) & 7) << 4));
                stm_x4(a, acc[mt][qb + 0][g], acc[mt][qb + 1][g],
                          acc[mt][qb + 2][g], acc[mt][qb + 3][g]);
            }
        __syncwarp();

#pragma unroll
        for (int k = 0; k < 4; k++) {
            int r = k * 4 + prow;            // 0..15
            int g = r >> 3, rr = r & 7;
            uint32_t a = wstage + (uint32_t)((g * 8 + pcol) * 128 +
                         (((rr + pcol) & 7) << 4));
            uint4 raw = *(const uint4*)(smem + (a - sb));
            int row = wm * 64 + mt * 16 + r;
            float xn = xn_s[row];
            ull nxn2 = pk2(-xn, -xn);

            float o[8];
#pragma unroll
            for (int j = 0; j < 4; j++) {
                uint32_t rj = (&raw.x)[j];
                float2 d = __half22float2(*reinterpret_cast<__half2*>(&rj));
                ull d2 = pk2(d.x, d.y);
                ull nu2 = add2p(nxn2, ncn2[j]);           // -(xn+cn)
                ull t2 = fma2p(d2, TWO2, nu2);            // 2d - xn - cn
                ull a2 = mul2p(t2, ivl2[j]);              // * iv*log2e
                float lo, hi;
                upk2(a2, lo, hi);
                o[j * 2 + 0] = ex2a(lo);
                o[j * 2 + 1] = ex2a(hi);
            }
            float* op = out + (size_t)(bm + row) * OUT_DIM + bn + wn * 64 + pcol * 8;
            *(float4*)(op)     = make_float4(o[0], o[1], o[2], o[3]);
            *(float4*)(op + 4) = make_float4(o[4], o[5], o[6], o[7]);
        }
        __syncwarp();
    }
}

extern "C" void kernel_launch(void* const* d_in, const int* in_sizes, int n_in,
                              void* d_out, int out_size) {
    const float* x  = (const float*)d_in[0];
    const float* c  = (const float*)d_in[1];
    const float* ls = (const float*)d_in[2];
    float* out = (float*)d_out;
    (void)in_sizes; (void)n_in; (void)out_size;

    cudaFuncSetAttribute(rbf_mma, cudaFuncAttributeMaxDynamicSharedMemorySize, SMEM_TOTAL);

    prep_all<<<(B_ROWS + OUT_DIM) / 8, 256>>>(x, c, ls);

    dim3 grid(OUT_DIM / BN, B_ROWS / BM);
    rbf_mma<<<grid, 256, SMEM_TOTAL>>>(out);
}

// round 14
// speedup vs baseline: 1.0293x; 1.0293x over previous
#include <cuda_runtime.h>
#include <cuda_fp16.h>
#include <cstdint>

#define B_ROWS 16384
#define IN_DIM 64
#define OUT_DIM 4096
#define BM 128
#define BN 256

// ---- device-global scratch (alloc-guard-safe) ----
__device__ __half g_xh[B_ROWS * IN_DIM];
__device__ __half g_ch[OUT_DIM * IN_DIM];
__device__ float g_xn[B_ROWS];
__device__ float g_cn[OUT_DIM];
__device__ float g_iv[OUT_DIM];

// ---- smem layout (bytes) ----
#define SA      0            // 16KB (128 rows x 128B)
#define SB      16384        // 32KB (256 rows x 128B)
#define S_XN    49152        // 512B
#define S_CN    49664        // 1KB (256 f32)
#define S_IV    50688        // 1KB
#define S_STAGE 51712        // 8 warps x 2KB
#define SMEM_TOTAL 68096

__device__ __forceinline__ uint32_t s2u(const void* p) {
    uint32_t a;
    asm("{ .reg .u64 t; cvta.to.shared.u64 t, %1; cvt.u32.u64 %0, t; }" : "=r"(a) : "l"(p));
    return a;
}
__device__ __forceinline__ void cp16(uint32_t dst, const void* src) {
    asm volatile("cp.async.cg.shared.global [%0], [%1], 16;" :: "r"(dst), "l"(src));
}
__device__ __forceinline__ void ldm_x4(uint32_t* r, uint32_t addr) {
    asm volatile("ldmatrix.sync.aligned.m8n8.x4.shared.b16 {%0,%1,%2,%3}, [%4];"
                 : "=r"(r[0]), "=r"(r[1]), "=r"(r[2]), "=r"(r[3]) : "r"(addr));
}
__device__ __forceinline__ void stm_x4(uint32_t addr, uint32_t r0, uint32_t r1,
                                       uint32_t r2, uint32_t r3) {
    asm volatile("stmatrix.sync.aligned.m8n8.x4.shared.b16 [%0], {%1,%2,%3,%4};"
                 :: "r"(addr), "r"(r0), "r"(r1), "r"(r2), "r"(r3) : "memory");
}
__device__ __forceinline__ void mma_h(uint32_t* c, const uint32_t* a,
                                      uint32_t b0, uint32_t b1) {
    asm volatile(
        "mma.sync.aligned.m16n8k16.row.col.f16.f16.f16.f16 "
        "{%0,%1}, {%2,%3,%4,%5}, {%6,%7}, {%0,%1};"
        : "+r"(c[0]), "+r"(c[1])
        : "r"(a[0]), "r"(a[1]), "r"(a[2]), "r"(a[3]), "r"(b0), "r"(b1));
}
__device__ __forceinline__ float ex2a(float x) {
    float r;
    asm("ex2.approx.f32 %0, %1;" : "=f"(r) : "f"(x));
    return r;
}

// ---- prep (fused): f32 -> fp16, row norms, inv_sigma2 ----
__global__ void prep_all(const float* __restrict__ x, const float* __restrict__ c,
                         const float* __restrict__ ls) {
    int gw = (blockIdx.x * blockDim.x + threadIdx.x) >> 5;
    int lane = threadIdx.x & 31;
    const float* src;
    __half2* dst;
    int row;
    if (gw < B_ROWS) {
        row = gw; src = x; dst = (__half2*)g_xh;
    } else {
        row = gw - B_ROWS;
        if (row >= OUT_DIM) return;
        src = c; dst = (__half2*)g_ch;
    }
    float2 v = ((const float2*)src)[row * 32 + lane];
    dst[row * 32 + lane] = __floats2half2_rn(v.x, v.y);
    float s = v.x * v.x + v.y * v.y;
#pragma unroll
    for (int o = 16; o; o >>= 1) s += __shfl_xor_sync(0xffffffffu, s, o);
    if (lane == 0) {
        if (gw < B_ROWS) g_xn[row] = s;
        else { g_cn[row] = s; g_iv[row] = __expf(-2.0f * ls[row]); }
    }
}

// ---- main: 128x256 tile, 64x64 warp tiles, f16-acc mma, cp.async loads ----
__global__ void __launch_bounds__(256, 2)
rbf_mma(float* __restrict__ out) {
    extern __shared__ char smem[];
    const uint32_t sb = s2u(smem);
    const int tid = threadIdx.x;
    const int bn = blockIdx.x * BN;
    const int bm = blockIdx.y * BM;

    // ---- global -> smem via cp.async, XOR-swizzled (q -> q ^ (row&7)) ----
    {
        const __half* ax = g_xh + (size_t)bm * IN_DIM;
        const __half* bc = g_ch + (size_t)bn * IN_DIM;
#pragma unroll
        for (int i = 0; i < 4; i++) {
            int l = tid + i * 256;
            int row = l >> 3, q = l & 7;
            cp16(sb + SA + row * 128 + ((q ^ (row & 7)) << 4), ax + l * 8);
        }
#pragma unroll
        for (int i = 0; i < 8; i++) {
            int l = tid + i * 256;
            int row = l >> 3, q = l & 7;
            cp16(sb + SB + row * 128 + ((q ^ (row & 7)) << 4), bc + l * 8);
        }
        if (tid < 32)       cp16(sb + S_XN + tid * 16, g_xn + bm + tid * 4);
        else if (tid < 96)  cp16(sb + S_CN + (tid - 32) * 16, g_cn + bn + (tid - 32) * 4);
        else if (tid < 160) cp16(sb + S_IV + (tid - 96) * 16, g_iv + bn + (tid - 96) * 4);
        asm volatile("cp.async.commit_group;" ::: "memory");
        asm volatile("cp.async.wait_group 0;" ::: "memory");
    }
    __syncthreads();

    const int wid = tid >> 5, lane = tid & 31;
    const int wm = wid >> 2, wn = wid & 3;   // 2x4 warp grid, 64x64 warp tiles
    const int lrow = lane & 15;
    const int ksel = lane >> 4;
    const int szk = lrow & 7;

    uint32_t aBase[4], bBase[4];
#pragma unroll
    for (int t = 0; t < 4; t++) {
        aBase[t] = sb + SA + (wm * 64 + t * 16 + lrow) * 128;
        bBase[t] = sb + SB + (wn * 64 + t * 16 + lrow) * 128;
    }

    uint32_t acc[4][8][2];                   // f16x2-packed accumulators
#pragma unroll
    for (int i = 0; i < 4; i++)
#pragma unroll
        for (int j = 0; j < 8; j++) { acc[i][j][0] = 0u; acc[i][j][1] = 0u; }

#pragma unroll
    for (int ks = 0; ks < 4; ks++) {
        const int kc = ks * 2 + ksel;
        const uint32_t ko = (uint32_t)((kc ^ szk) << 4);
        uint32_t Ah[4][4], Bh[4][4];
#pragma unroll
        for (int t = 0; t < 4; t++) ldm_x4(Ah[t], aBase[t] + ko);
#pragma unroll
        for (int t = 0; t < 4; t++) ldm_x4(Bh[t], bBase[t] + ko);
#pragma unroll
        for (int mt = 0; mt < 4; mt++)
#pragma unroll
            for (int p = 0; p < 4; p++) {
                mma_h(acc[mt][p * 2 + 0], Ah[mt], Bh[p][0], Bh[p][2]);
                mma_h(acc[mt][p * 2 + 1], Ah[mt], Bh[p][1], Bh[p][3]);
            }
    }

    // ---- epilogue: swizzled matrix-major stage, scalar math, no clamp ----
    const float* xn_s = (const float*)(smem + S_XN);
    const float* cn_s = (const float*)(smem + S_CN);
    const float* iv_s = (const float*)(smem + S_IV);
    const float L2E = 1.4426950408889634f;

    const int prow = lane >> 3;          // 0..3
    const int pcol = lane & 7;           // matrix index / col-chunk
    float cn8[8], ivl8[8];
#pragma unroll
    for (int j = 0; j < 8; j++) {
        int col = wn * 64 + pcol * 8 + j;
        cn8[j] = cn_s[col];
        ivl8[j] = iv_s[col] * L2E;
    }

    const uint32_t wstage = sb + S_STAGE + wid * 2048;
    const int m_loc = lane >> 3;
    const int rr_s = lane & 7;

#pragma unroll
    for (int mt = 0; mt < 4; mt++) {
#pragma unroll
        for (int g = 0; g < 2; g++)
#pragma unroll
            for (int qb = 0; qb < 8; qb += 4) {
                int m = qb + m_loc;
                uint32_t a = wstage + (uint32_t)((g * 8 + m) * 128 +
                             (((rr_s + m) & 7) << 4));
                stm_x4(a, acc[mt][qb + 0][g], acc[mt][qb + 1][g],
                          acc[mt][qb + 2][g], acc[mt][qb + 3][g]);
            }
        __syncwarp();

#pragma unroll
        for (int k = 0; k < 4; k++) {
            int r = k * 4 + prow;            // 0..15
            int g = r >> 3, rr = r & 7;
            uint32_t a = wstage + (uint32_t)((g * 8 + pcol) * 128 +
                         (((rr + pcol) & 7) << 4));
            uint4 raw = *(const uint4*)(smem + (a - sb));
            float2 f0 = __half22float2(*reinterpret_cast<__half2*>(&raw.x));
            float2 f1 = __half22float2(*reinterpret_cast<__half2*>(&raw.y));
            float2 f2 = __half22float2(*reinterpret_cast<__half2*>(&raw.z));
            float2 f3 = __half22float2(*reinterpret_cast<__half2*>(&raw.w));
            int row = wm * 64 + mt * 16 + r;
            float xn = xn_s[row];
            float4 o0, o1;
            o0.x = ex2a(fmaf(2.f, f0.x, -(xn + cn8[0])) * ivl8[0]);
            o0.y = ex2a(fmaf(2.f, f0.y, -(xn + cn8[1])) * ivl8[1]);
            o0.z = ex2a(fmaf(2.f, f1.x, -(xn + cn8[2])) * ivl8[2]);
            o0.w = ex2a(fmaf(2.f, f1.y, -(xn + cn8[3])) * ivl8[3]);
            o1.x = ex2a(fmaf(2.f, f2.x, -(xn + cn8[4])) * ivl8[4]);
            o1.y = ex2a(fmaf(2.f, f2.y, -(xn + cn8[5])) * ivl8[5]);
            o1.z = ex2a(fmaf(2.f, f3.x, -(xn + cn8[6])) * ivl8[6]);
            o1.w = ex2a(fmaf(2.f, f3.y, -(xn + cn8[7])) * ivl8[7]);
            float* op = out + (size_t)(bm + row) * OUT_DIM + bn + wn * 64 + pcol * 8;
            *(float4*)(op) = o0;
            *(float4*)(op + 4) = o1;
        }
        __syncwarp();
    }
}

extern "C" void kernel_launch(void* const* d_in, const int* in_sizes, int n_in,
                              void* d_out, int out_size) {
    const float* x  = (const float*)d_in[0];
    const float* c  = (const float*)d_in[1];
    const float* ls = (const float*)d_in[2];
    float* out = (float*)d_out;
    (void)in_sizes; (void)n_in; (void)out_size;

    cudaFuncSetAttribute(rbf_mma, cudaFuncAttributeMaxDynamicSharedMemorySize, SMEM_TOTAL);

    prep_all<<<(B_ROWS + OUT_DIM) / 8, 256>>>(x, c, ls);

    dim3 grid(OUT_DIM / BN, B_ROWS / BM);
    rbf_mma<<<grid, 256, SMEM_TOTAL>>>(out);
}